// round 2
// baseline (speedup 1.0000x reference)
#include <cuda_runtime.h>
#include <cstdint>

// Problem constants
#define BB 64
#define SS 512
#define HH 768
#define EE 128
#define TT_ 4
#define NT 5
#define H4 192   // H/4 float4 lanes

// Scratch (no allocs allowed)
__device__ float g_rowcoef[BB * SS * 8];   // {at0..at4, ac, 0, 0} per (b,s)

// ---------------------------------------------------------------------------
// P: per-batch coefficient build. One block per batch b (512 threads, one per
// flat (e,t)). Histogram into smem via atomics, then write 512 rows x 8 floats.
// ---------------------------------------------------------------------------
__global__ void __launch_bounds__(512) rowcoef_kernel(
    const int* __restrict__ ent_tokens,     // [E,T]
    const int* __restrict__ types,          // [B,E]
    const float* __restrict__ conf) {       // [B,E]
    __shared__ float sm[SS * 6];
    int b = blockIdx.x;
    int tid = threadIdx.x;                  // 0..511 == flat (e,t)

#pragma unroll
    for (int j = 0; j < 6; j++) sm[tid + j * SS] = 0.f;
    __syncthreads();

    int tok = ent_tokens[tid];
    int e = tid >> 2;
    int ty = types[b * EE + e];
    float c = conf[b * EE + e];
    atomicAdd(&sm[tok * 6 + ty], 1.f);
    atomicAdd(&sm[tok * 6 + 5], c);
    __syncthreads();

    // thread tid writes row s=tid (two float4 stores)
    float4* o = reinterpret_cast<float4*>(&g_rowcoef[((size_t)b * SS + tid) * 8]);
    o[0] = make_float4(sm[tid * 6 + 0], sm[tid * 6 + 1], sm[tid * 6 + 2], sm[tid * 6 + 3]);
    o[1] = make_float4(sm[tid * 6 + 4], sm[tid * 6 + 5], 0.f, 0.f);
}

// ---------------------------------------------------------------------------
// Fused main kernel. Task list per batch b: 512 enhance-row tasks then 128
// entity-embedding tasks (computed directly from hidden + coefficients, so no
// dependency on the enhanced output; gather reads hit L2 since the same
// batch's rows were just streamed by the enhance tasks).
// Each thread owns a fixed float4 h-lane; tables live in registers.
// ---------------------------------------------------------------------------
__global__ void __launch_bounds__(H4) fused_kernel(
    const float* __restrict__ hidden,       // [B,S,H]
    const int* __restrict__ ent_tokens,     // [E,T]
    const float* __restrict__ type_table,   // [NT,H]
    const float* __restrict__ conf_w,       // [H]
    const float* __restrict__ conf_b,       // [H]
    float* __restrict__ out_enh,            // [B,S,H]
    float* __restrict__ out_emb) {          // [B,E,H]
    int tid = threadIdx.x;                  // 0..191
    int h = tid * 4;

    float4 cb4 = *reinterpret_cast<const float4*>(conf_b + h);
    float4 cw4 = *reinterpret_cast<const float4*>(conf_w + h);
    float4 ttc[NT];
#pragma unroll
    for (int ty = 0; ty < NT; ty++) {
        float4 v = *reinterpret_cast<const float4*>(type_table + ty * HH + h);
        ttc[ty] = make_float4(v.x + cb4.x, v.y + cb4.y, v.z + cb4.z, v.w + cb4.w);
    }

    int idx = blockIdx.x;                   // 0 .. B*(S+E)-1
    int b = idx / (SS + EE);
    int r = idx - b * (SS + EE);
    const float* hb = hidden + (size_t)b * SS * HH;

    if (r < SS) {
        // ---- enhance row (b, s=r) ----
        int s = r;
        const float4* cf = reinterpret_cast<const float4*>(
            &g_rowcoef[((size_t)b * SS + s) * 8]);
        float4 c0 = __ldg(cf);
        float4 c1 = __ldg(cf + 1);
        float4 v = *reinterpret_cast<const float4*>(hb + (size_t)s * HH + h);
        float a0 = c0.x, a1 = c0.y, a2 = c0.z, a3 = c0.w, a4 = c1.x, ac = c1.y;
        v.x += a0 * ttc[0].x + a1 * ttc[1].x + a2 * ttc[2].x + a3 * ttc[3].x + a4 * ttc[4].x + ac * cw4.x;
        v.y += a0 * ttc[0].y + a1 * ttc[1].y + a2 * ttc[2].y + a3 * ttc[3].y + a4 * ttc[4].y + ac * cw4.y;
        v.z += a0 * ttc[0].z + a1 * ttc[1].z + a2 * ttc[2].z + a3 * ttc[3].z + a4 * ttc[4].z + ac * cw4.z;
        v.w += a0 * ttc[0].w + a1 * ttc[1].w + a2 * ttc[2].w + a3 * ttc[3].w + a4 * ttc[4].w + ac * cw4.w;
        *reinterpret_cast<float4*>(out_enh + ((size_t)b * SS + s) * HH + h) = v;
    } else {
        // ---- entity embedding (b, e) : 0.25 * sum_t enhanced[b, tok, :] ----
        int e = r - SS;
        float4 acc = make_float4(0.f, 0.f, 0.f, 0.f);
        float a0 = 0.f, a1 = 0.f, a2 = 0.f, a3 = 0.f, a4 = 0.f, ac = 0.f;
#pragma unroll
        for (int t = 0; t < TT_; t++) {
            int s = __ldg(&ent_tokens[e * TT_ + t]);
            // sum coefficients for the contribution part
            const float4* cf = reinterpret_cast<const float4*>(
                &g_rowcoef[((size_t)b * SS + s) * 8]);
            float4 c0 = __ldg(cf);
            float4 c1 = __ldg(cf + 1);
            a0 += c0.x; a1 += c0.y; a2 += c0.z; a3 += c0.w; a4 += c1.x; ac += c1.y;
            // sum hidden rows (L2-resident: same batch just streamed)
            float4 v = *reinterpret_cast<const float4*>(hb + (size_t)s * HH + h);
            acc.x += v.x; acc.y += v.y; acc.z += v.z; acc.w += v.w;
        }
        acc.x += a0 * ttc[0].x + a1 * ttc[1].x + a2 * ttc[2].x + a3 * ttc[3].x + a4 * ttc[4].x + ac * cw4.x;
        acc.y += a0 * ttc[0].y + a1 * ttc[1].y + a2 * ttc[2].y + a3 * ttc[3].y + a4 * ttc[4].y + ac * cw4.y;
        acc.z += a0 * ttc[0].z + a1 * ttc[1].z + a2 * ttc[2].z + a3 * ttc[3].z + a4 * ttc[4].z + ac * cw4.z;
        acc.w += a0 * ttc[0].w + a1 * ttc[1].w + a2 * ttc[2].w + a3 * ttc[3].w + a4 * ttc[4].w + ac * cw4.w;
        acc.x *= 0.25f; acc.y *= 0.25f; acc.z *= 0.25f; acc.w *= 0.25f;
        *reinterpret_cast<float4*>(out_emb + ((size_t)b * EE + e) * HH + h) = acc;
    }
}

// ---------------------------------------------------------------------------
// Inputs in metadata order:
// 0 hidden_states (B,S,H) f32 | 1 entity_types (B,E) i32 | 2 entity_confidences (B,E) f32
// 3 ent_tokens (E,T) i32 | 4 type_table (NT,H) f32 | 5 conf_w (1,H) f32 | 6 conf_b (H) f32
// Output: enhanced (B,S,H) then entity_embeddings (B,E,H), concatenated.
// ---------------------------------------------------------------------------
extern "C" void kernel_launch(void* const* d_in, const int* in_sizes, int n_in,
                              void* d_out, int out_size) {
    const float* hidden   = (const float*)d_in[0];
    const int*   types    = (const int*)d_in[1];
    const float* conf     = (const float*)d_in[2];
    const int*   ent_tok  = (const int*)d_in[3];
    const float* ttab     = (const float*)d_in[4];
    const float* conf_w   = (const float*)d_in[5];
    const float* conf_b   = (const float*)d_in[6];

    float* out_enh = (float*)d_out;
    float* out_emb = out_enh + (size_t)BB * SS * HH;

    rowcoef_kernel<<<BB, 512>>>(ent_tok, types, conf);
    fused_kernel<<<BB * (SS + EE), H4>>>(hidden, ent_tok, ttab, conf_w, conf_b,
                                         out_enh, out_emb);
}

// round 3
// speedup vs baseline: 1.3500x; 1.3500x over previous
#include <cuda_runtime.h>
#include <cstdint>

// Problem constants
#define BB 64
#define SS 512
#define HH 768
#define EE 128
#define TT_ 4
#define NT 5
#define H4 192   // H/4 float4 lanes

// Scratch (no allocs allowed)
__device__ float g_rowcoef[BB * SS * 8];   // {at0..at4, ac, 0, 0} per (b,s)

// ---------------------------------------------------------------------------
// P: per-batch coefficient build. One block per batch b (512 threads, one per
// flat (e,t)). Histogram into smem via atomics, then write 512 rows x 8 floats.
// ---------------------------------------------------------------------------
__global__ void __launch_bounds__(512) rowcoef_kernel(
    const int* __restrict__ ent_tokens,     // [E,T]
    const int* __restrict__ types,          // [B,E]
    const float* __restrict__ conf) {       // [B,E]
    __shared__ float sm[SS * 6];
    int b = blockIdx.x;
    int tid = threadIdx.x;                  // 0..511 == flat (e,t)

#pragma unroll
    for (int j = 0; j < 6; j++) sm[tid + j * SS] = 0.f;
    __syncthreads();

    int tok = ent_tokens[tid];
    int e = tid >> 2;
    int ty = types[b * EE + e];
    float c = conf[b * EE + e];
    atomicAdd(&sm[tok * 6 + ty], 1.f);
    atomicAdd(&sm[tok * 6 + 5], c);
    __syncthreads();

    float4* o = reinterpret_cast<float4*>(&g_rowcoef[((size_t)b * SS + tid) * 8]);
    o[0] = make_float4(sm[tid * 6 + 0], sm[tid * 6 + 1], sm[tid * 6 + 2], sm[tid * 6 + 3]);
    o[1] = make_float4(sm[tid * 6 + 4], sm[tid * 6 + 5], 0.f, 0.f);
}

// ---------------------------------------------------------------------------
// Fused main kernel (persistent grid-stride). Task list per batch b:
// 512 enhance-row tasks then 128 entity-embedding tasks. Emb tasks compute
// directly from hidden + coefficients (no dependency on enhanced output);
// their hidden reads hit L2 because the same batch's rows were just streamed
// by the enhance tasks running concurrently/just-before in task order.
// Tables live in registers, loaded once per block (amortized over ~46 tasks).
// ---------------------------------------------------------------------------
__global__ void __launch_bounds__(H4) fused_kernel(
    const float* __restrict__ hidden,       // [B,S,H]
    const int* __restrict__ ent_tokens,     // [E,T]
    const float* __restrict__ type_table,   // [NT,H]
    const float* __restrict__ conf_w,       // [H]
    const float* __restrict__ conf_b,       // [H]
    float* __restrict__ out_enh,            // [B,S,H]
    float* __restrict__ out_emb) {          // [B,E,H]
    int tid = threadIdx.x;                  // 0..191
    int h = tid * 4;

    float4 cb4 = *reinterpret_cast<const float4*>(conf_b + h);
    float4 cw4 = *reinterpret_cast<const float4*>(conf_w + h);
    float4 ttc[NT];
#pragma unroll
    for (int ty = 0; ty < NT; ty++) {
        float4 v = *reinterpret_cast<const float4*>(type_table + ty * HH + h);
        ttc[ty] = make_float4(v.x + cb4.x, v.y + cb4.y, v.z + cb4.z, v.w + cb4.w);
    }

    const int NTASK = BB * (SS + EE);
    for (int idx = blockIdx.x; idx < NTASK; idx += gridDim.x) {
        int b = idx / (SS + EE);
        int r = idx - b * (SS + EE);
        const float* hb = hidden + (size_t)b * SS * HH;

        if (r < SS) {
            // ---- enhance row (b, s=r) ----
            int s = r;
            const float4* cf = reinterpret_cast<const float4*>(
                &g_rowcoef[((size_t)b * SS + s) * 8]);
            float4 c0 = __ldg(cf);
            float4 c1 = __ldg(cf + 1);
            float4 v = *reinterpret_cast<const float4*>(hb + (size_t)s * HH + h);
            float a0 = c0.x, a1 = c0.y, a2 = c0.z, a3 = c0.w, a4 = c1.x, ac = c1.y;
            v.x += a0 * ttc[0].x + a1 * ttc[1].x + a2 * ttc[2].x + a3 * ttc[3].x + a4 * ttc[4].x + ac * cw4.x;
            v.y += a0 * ttc[0].y + a1 * ttc[1].y + a2 * ttc[2].y + a3 * ttc[3].y + a4 * ttc[4].y + ac * cw4.y;
            v.z += a0 * ttc[0].z + a1 * ttc[1].z + a2 * ttc[2].z + a3 * ttc[3].z + a4 * ttc[4].z + ac * cw4.z;
            v.w += a0 * ttc[0].w + a1 * ttc[1].w + a2 * ttc[2].w + a3 * ttc[3].w + a4 * ttc[4].w + ac * cw4.w;
            *reinterpret_cast<float4*>(out_enh + ((size_t)b * SS + s) * HH + h) = v;
        } else {
            // ---- entity embedding (b, e): 0.25 * sum_t enhanced[b, tok, :] ----
            int e = r - SS;
            float4 acc = make_float4(0.f, 0.f, 0.f, 0.f);
            float a0 = 0.f, a1 = 0.f, a2 = 0.f, a3 = 0.f, a4 = 0.f, ac = 0.f;
#pragma unroll
            for (int t = 0; t < TT_; t++) {
                int s = __ldg(&ent_tokens[e * TT_ + t]);
                const float4* cf = reinterpret_cast<const float4*>(
                    &g_rowcoef[((size_t)b * SS + s) * 8]);
                float4 c0 = __ldg(cf);
                float4 c1 = __ldg(cf + 1);
                a0 += c0.x; a1 += c0.y; a2 += c0.z; a3 += c0.w; a4 += c1.x; ac += c1.y;
                float4 v = *reinterpret_cast<const float4*>(hb + (size_t)s * HH + h);
                acc.x += v.x; acc.y += v.y; acc.z += v.z; acc.w += v.w;
            }
            acc.x += a0 * ttc[0].x + a1 * ttc[1].x + a2 * ttc[2].x + a3 * ttc[3].x + a4 * ttc[4].x + ac * cw4.x;
            acc.y += a0 * ttc[0].y + a1 * ttc[1].y + a2 * ttc[2].y + a3 * ttc[3].y + a4 * ttc[4].y + ac * cw4.y;
            acc.z += a0 * ttc[0].z + a1 * ttc[1].z + a2 * ttc[2].z + a3 * ttc[3].z + a4 * ttc[4].z + ac * cw4.z;
            acc.w += a0 * ttc[0].w + a1 * ttc[1].w + a2 * ttc[2].w + a3 * ttc[3].w + a4 * ttc[4].w + ac * cw4.w;
            acc.x *= 0.25f; acc.y *= 0.25f; acc.z *= 0.25f; acc.w *= 0.25f;
            *reinterpret_cast<float4*>(out_emb + ((size_t)b * EE + e) * HH + h) = acc;
        }
    }
}

// ---------------------------------------------------------------------------
// Inputs in metadata order:
// 0 hidden_states (B,S,H) f32 | 1 entity_types (B,E) i32 | 2 entity_confidences (B,E) f32
// 3 ent_tokens (E,T) i32 | 4 type_table (NT,H) f32 | 5 conf_w (1,H) f32 | 6 conf_b (H) f32
// Output: enhanced (B,S,H) then entity_embeddings (B,E,H), concatenated.
// ---------------------------------------------------------------------------
extern "C" void kernel_launch(void* const* d_in, const int* in_sizes, int n_in,
                              void* d_out, int out_size) {
    const float* hidden   = (const float*)d_in[0];
    const int*   types    = (const int*)d_in[1];
    const float* conf     = (const float*)d_in[2];
    const int*   ent_tok  = (const int*)d_in[3];
    const float* ttab     = (const float*)d_in[4];
    const float* conf_w   = (const float*)d_in[5];
    const float* conf_b   = (const float*)d_in[6];

    float* out_enh = (float*)d_out;
    float* out_emb = out_enh + (size_t)BB * SS * HH;

    rowcoef_kernel<<<BB, 512>>>(ent_tok, types, conf);
    fused_kernel<<<888, H4>>>(hidden, ent_tok, ttab, conf_w, conf_b,
                              out_enh, out_emb);
}